// round 1
// baseline (speedup 1.0000x reference)
#include <cuda_runtime.h>

// ---------------------------------------------------------------------------
// SINDy autoencoder forward:
//   z = enc(x); dz = J_enc(x) @ dx (forward-mode JVP)
//   theta = sindy_library(z); dzb = E_w @ theta + E_b
//   xb = dec(z); dxb = J_dec(z) @ dzb (forward-mode JVP)
// Output layout: [z(16) | dz(16) | dzb(16) | xb(16384) | dxb(16384)] = 32816 f32
//
// Memory-bound: ~545MB of weights per call. Every weight is loaded once and
// used for two FMAs (primal + tangent dual matvec).
// ---------------------------------------------------------------------------

#define W0_OUT 4096
#define W0_IN  16384
#define W1_OUT 1024
#define W1_IN  4096
#define LATENT 16
#define SINDY_DIM 984   // 16 ones + 16 z + 136 quad + 816 cubic

// Scratch (device globals; no allocation allowed)
__device__ float g_pre1[W0_OUT], g_u1[W0_OUT];   // enc layer0 raw outputs
__device__ float g_pre2[W1_OUT], g_u2[W1_OUT];   // enc layer1 raw outputs
__device__ float g_g1[1024],     g_p1[1024];     // dec layer0 activated outputs
__device__ float g_q2[4096],     g_v2[4096];     // dec layer1 raw outputs

__device__ __forceinline__ float sigf(float x) { return 1.0f / (1.0f + __expf(-x)); }

// ---------------------------------------------------------------------------
// Dual matvec: outA = W @ a (+bias), outB = W @ b, one pass over W.
// If SIG: a := sigmoid(a_raw), b := a*(1-a)*b_raw  (element-wise, on the fly)
// ROWS rows per block; THREADS threads; K columns (multiple of THREADS*4).
// ---------------------------------------------------------------------------
template<int K, int ROWS, int THREADS, bool SIG>
__device__ __forceinline__ void dual_matvec_body(
    const float* __restrict__ W,
    const float* __restrict__ av,
    const float* __restrict__ bv,
    const float* __restrict__ bias,
    float* __restrict__ outA,
    float* __restrict__ outB)
{
    constexpr int NW = THREADS / 32;
    constexpr int ITERS = K / (THREADS * 4);
    const int tid  = threadIdx.x;
    const int row0 = blockIdx.x * ROWS;

    float accA[ROWS], accB[ROWS];
#pragma unroll
    for (int r = 0; r < ROWS; r++) { accA[r] = 0.0f; accB[r] = 0.0f; }

#pragma unroll 4
    for (int it = 0; it < ITERS; it++) {
        const int k = (it * THREADS + tid) * 4;
        float4 a4 = *(const float4*)(av + k);
        float4 b4 = *(const float4*)(bv + k);
        if (SIG) {
            float s;
            s = sigf(a4.x); b4.x *= s * (1.0f - s); a4.x = s;
            s = sigf(a4.y); b4.y *= s * (1.0f - s); a4.y = s;
            s = sigf(a4.z); b4.z *= s * (1.0f - s); a4.z = s;
            s = sigf(a4.w); b4.w *= s * (1.0f - s); a4.w = s;
        }
#pragma unroll
        for (int r = 0; r < ROWS; r++) {
            const float4 w4 = *(const float4*)(W + (size_t)(row0 + r) * K + k);
            accA[r] = fmaf(w4.x, a4.x, accA[r]);
            accA[r] = fmaf(w4.y, a4.y, accA[r]);
            accA[r] = fmaf(w4.z, a4.z, accA[r]);
            accA[r] = fmaf(w4.w, a4.w, accA[r]);
            accB[r] = fmaf(w4.x, b4.x, accB[r]);
            accB[r] = fmaf(w4.y, b4.y, accB[r]);
            accB[r] = fmaf(w4.z, b4.z, accB[r]);
            accB[r] = fmaf(w4.w, b4.w, accB[r]);
        }
    }

    __shared__ float sA[NW][ROWS], sB[NW][ROWS];
    const int lane = tid & 31, warp = tid >> 5;
#pragma unroll
    for (int r = 0; r < ROWS; r++) {
        float vA = accA[r], vB = accB[r];
#pragma unroll
        for (int o = 16; o; o >>= 1) {
            vA += __shfl_xor_sync(0xffffffffu, vA, o);
            vB += __shfl_xor_sync(0xffffffffu, vB, o);
        }
        if (lane == 0) { sA[warp][r] = vA; sB[warp][r] = vB; }
    }
    __syncthreads();
    if (tid < ROWS) {
        float vA = 0.0f, vB = 0.0f;
#pragma unroll
        for (int w = 0; w < NW; w++) { vA += sA[w][tid]; vB += sB[w][tid]; }
        vA += bias[row0 + tid];
        outA[row0 + tid] = vA;
        outB[row0 + tid] = vB;
    }
}

// enc layer 0: pre1 = W0 @ x + b0 ; u1 = W0 @ dx
__global__ void __launch_bounds__(256) k_enc0(
    const float* __restrict__ W, const float* __restrict__ x,
    const float* __restrict__ dx, const float* __restrict__ b)
{
    dual_matvec_body<W0_IN, 8, 256, false>(W, x, dx, b, g_pre1, g_u1);
}

// enc layer 1 (sigmoid fused on inputs): pre2 = W1 @ h1 + b1 ; u2 = W1 @ t1
__global__ void __launch_bounds__(256) k_enc1(
    const float* __restrict__ W, const float* __restrict__ b)
{
    dual_matvec_body<W0_OUT, 8, 256, true>(W, g_pre1, g_u1, b, g_pre2, g_u2);
}

// dec layer 1: q2 = Wd1 @ g1 + bd1 ; v2 = Wd1 @ p1  (g1,p1 already activated)
__global__ void __launch_bounds__(256) k_dec1(
    const float* __restrict__ W, const float* __restrict__ b)
{
    dual_matvec_body<1024, 8, 256, false>(W, g_g1, g_p1, b, g_q2, g_v2);
}

// dec layer 2 (sigmoid fused): xb = Wd2 @ g2 + bd2 ; dxb = Wd2 @ p2
__global__ void __launch_bounds__(256) k_dec2(
    const float* __restrict__ W, const float* __restrict__ b,
    float* __restrict__ out)
{
    dual_matvec_body<4096, 8, 256, true>(W, g_q2, g_v2, b, out + 48, out + 48 + 16384);
}

// ---------------------------------------------------------------------------
// Small middle chain, one block, 512 threads:
//   h2/t2 -> z,dz -> theta -> dzb -> dec layer0 (g1,p1)
// ---------------------------------------------------------------------------
__global__ void __launch_bounds__(512) k_small(
    const float* __restrict__ we_w2, const float* __restrict__ we_b2,
    const float* __restrict__ E_w,   const float* __restrict__ E_b,
    const float* __restrict__ wd_w0, const float* __restrict__ wd_b0,
    float* __restrict__ out)
{
    __shared__ float h2[W1_OUT], t2[W1_OUT];
    __shared__ float z[LATENT], dz[LATENT], dzb[LATENT];
    __shared__ float theta[SINDY_DIM];

    const int tid = threadIdx.x;
    const int lane = tid & 31, wid = tid >> 5;   // 16 warps

    // stage 1: activation of enc layer 1
    for (int i = tid; i < W1_OUT; i += 512) {
        float s = sigf(g_pre2[i]);
        h2[i] = s;
        t2[i] = s * (1.0f - s) * g_u2[i];
    }
    __syncthreads();

    // stage 2: z = we_w2 @ h2 + b2 ; dz = we_w2 @ t2   (warp per row)
    {
        float az = 0.0f, ad = 0.0f;
        const float* wr = we_w2 + (size_t)wid * W1_OUT;
        for (int c = lane; c < W1_OUT; c += 32) {
            float w = wr[c];
            az = fmaf(w, h2[c], az);
            ad = fmaf(w, t2[c], ad);
        }
#pragma unroll
        for (int o = 16; o; o >>= 1) {
            az += __shfl_xor_sync(0xffffffffu, az, o);
            ad += __shfl_xor_sync(0xffffffffu, ad, o);
        }
        if (lane == 0) { z[wid] = az + we_b2[wid]; dz[wid] = ad; }
    }
    __syncthreads();

    if (tid < LATENT) { out[tid] = z[tid]; out[LATENT + tid] = dz[tid]; }

    // stage 3: theta = [ones, z, upper-tri pairs, upper-tri triples]
    for (int idx = tid; idx < SINDY_DIM; idx += 512) {
        float v;
        if (idx < 16) {
            v = 1.0f;
        } else if (idx < 32) {
            v = z[idx - 16];
        } else if (idx < 32 + 136) {
            int q = idx - 32, i = 0;
            for (;;) { int m = 16 - i; if (q < m) break; q -= m; i++; }
            v = z[i] * z[i + q];
        } else {
            int t = idx - 168, i = 0;
            for (;;) { int m = 16 - i; int c = m * (m + 1) / 2; if (t < c) break; t -= c; i++; }
            int j = i;
            for (;;) { int m = 16 - j; if (t < m) break; t -= m; j++; }
            v = z[i] * z[j] * z[j + t];
        }
        theta[idx] = v;
    }
    __syncthreads();

    // stage 4: dzb = E_w @ theta + E_b  (warp per row)
    {
        float a = 0.0f;
        const float* er = E_w + (size_t)wid * SINDY_DIM;
        for (int c = lane; c < SINDY_DIM; c += 32)
            a = fmaf(er[c], theta[c], a);
#pragma unroll
        for (int o = 16; o; o >>= 1)
            a += __shfl_xor_sync(0xffffffffu, a, o);
        if (lane == 0) dzb[wid] = a + E_b[wid];
    }
    __syncthreads();

    if (tid < LATENT) out[32 + tid] = dzb[tid];

    // stage 5: dec layer 0 + activation:
    //   q1 = wd_w0 @ z + bd0 ; v1 = wd_w0 @ dzb ; g1 = sig(q1) ; p1 = g1(1-g1)v1
    for (int row = tid; row < 1024; row += 512) {
        float a = wd_b0[row], bb = 0.0f;
        const float* wr = wd_w0 + (size_t)row * LATENT;
#pragma unroll
        for (int c = 0; c < LATENT; c++) {
            float w = wr[c];
            a  = fmaf(w, z[c],   a);
            bb = fmaf(w, dzb[c], bb);
        }
        float s = sigf(a);
        g_g1[row] = s;
        g_p1[row] = s * (1.0f - s) * bb;
    }
}

extern "C" void kernel_launch(void* const* d_in, const int* in_sizes, int n_in,
                              void* d_out, int out_size)
{
    const float* x     = (const float*)d_in[0];
    const float* dx    = (const float*)d_in[1];
    // d_in[2] = ddx (unused by the reference output)
    const float* we_w0 = (const float*)d_in[3];
    const float* we_b0 = (const float*)d_in[4];
    const float* we_w1 = (const float*)d_in[5];
    const float* we_b1 = (const float*)d_in[6];
    const float* we_w2 = (const float*)d_in[7];
    const float* we_b2 = (const float*)d_in[8];
    const float* wd_w0 = (const float*)d_in[9];
    const float* wd_b0 = (const float*)d_in[10];
    const float* wd_w1 = (const float*)d_in[11];
    const float* wd_b1 = (const float*)d_in[12];
    const float* wd_w2 = (const float*)d_in[13];
    const float* wd_b2 = (const float*)d_in[14];
    const float* E_w   = (const float*)d_in[15];
    const float* E_b   = (const float*)d_in[16];
    float* out = (float*)d_out;

    k_enc0<<<W0_OUT / 8, 256>>>(we_w0, x, dx, we_b0);        // 256MB weights
    k_enc1<<<W1_OUT / 8, 256>>>(we_w1, we_b1);               // 16MB
    k_small<<<1, 512>>>(we_w2, we_b2, E_w, E_b, wd_w0, wd_b0, out);
    k_dec1<<<4096 / 8, 256>>>(wd_w1, wd_b1);                 // 16MB
    k_dec2<<<16384 / 8, 256>>>(wd_w2, wd_b2, out);           // 256MB
}